// round 9
// baseline (speedup 1.0000x reference)
#include <cuda_runtime.h>
#include <cstdint>

// ---------------------------------------------------------------------------
// LightGCN / 2-layer GCN on GB300.
//   x = concat(user_emb, item_emb)            [N,64]
//   deg[c] = (# in-edges of c) + 1 (self loop);  dinv = rsqrt(deg)
//   layer: h = x@W;  g = h * dinv;  acc[c] = g[c] + sum_{e: col=c} g[row_e]
//          x_next = dinv * acc + b
// Fusions: norm split into pre/post dinv scaling; self-loop = acc initializer.
//
// R7 FIX: R3/R4 passed the __device__ symbol g_acc as a kernel argument from
// HOST code, which passes the host shadow address (ATS made the bogus writes
// silently land in host memory instead of faulting) -> layer-1 self-loop
// initialization was lost -> rel_err 0.545. All __device__ symbols are now
// resolved strictly inside device code (transform takes a `layer` selector).
// Vector RED reinstated (it was exonerated by the R3==R4 identical error).
// ---------------------------------------------------------------------------

#define D 64
#define MAXN 200064
#define MAXE 1200000

__device__ int   g_flag;                       // 1 => edge_index is int64
__device__ int   g_e32[2 * MAXE];              // [0,E): row, [E,2E): col
__device__ int   g_deg[MAXN];
__device__ float g_dinv[MAXN];
__device__ float g_g[(size_t)MAXN * D];        // pre-scaled transformed feats
__device__ float g_acc[(size_t)MAXN * D];      // layer-1 aggregation target

// --------------------------- dtype detection -------------------------------
// int64 little-endian with values < 2^31: every odd 32-bit word is 0.
// For int32 data the odd words are random node indices; all-256-zero is
// impossible (p ~ (1/200000)^256). g_flag=1 <=> 8-byte stride.
__global__ void detect_kernel(const unsigned int* __restrict__ raw) {
    __shared__ int any_nonzero;
    if (threadIdx.x == 0) any_nonzero = 0;
    __syncthreads();
    if (raw[2 * threadIdx.x + 1] != 0u) atomicExch(&any_nonzero, 1);
    __syncthreads();
    if (threadIdx.x == 0) g_flag = (any_nonzero == 0) ? 1 : 0;
}

__global__ void convert_kernel(const void* __restrict__ raw, int n2e, int N) {
    int i = blockIdx.x * blockDim.x + threadIdx.x;
    if (i >= n2e) return;
    long long v;
    if (g_flag) v = ((const long long*)raw)[i];
    else        v = (long long)((const int*)raw)[i];
    int vi = (int)v;
    if ((unsigned)vi >= (unsigned)N) vi = 0;   // corruption insurance
    g_e32[i] = vi;
}

// ------------------------------ degrees ------------------------------------
__global__ void deg_init_kernel(int n) {
    int i = blockIdx.x * blockDim.x + threadIdx.x;
    if (i < n) g_deg[i] = 1;                   // self-loop
}

__global__ void deg_count_kernel(int E) {
    int e = blockIdx.x * blockDim.x + threadIdx.x;
    if (e < E) atomicAdd(&g_deg[g_e32[E + e]], 1);
}

__global__ void dinv_kernel(int n) {
    int i = blockIdx.x * blockDim.x + threadIdx.x;
    if (i < n) g_dinv[i] = rsqrtf((float)g_deg[i]);   // deg >= 1 always
}

// ------------------------------ transform ----------------------------------
// Per block: 128 nodes x 64 cols. 256 threads; thread = (node_group 0..15) x
// (col4 0..15); each thread accumulates 8 nodes x 4 cols in registers.
// layer==1: input = embeddings, acc target = g_acc (device symbol, resolved
//           IN DEVICE CODE).
// layer==2: input = dinv*g_acc + b1, acc target = out (real harness pointer).
// Writes g = (x@W)*dinv to g_g AND initializes the acc target with the same
// value (the self-loop contribution).
__global__ __launch_bounds__(256) void transform_kernel(
    const float* __restrict__ user_emb,
    const float* __restrict__ item_emb,
    const float* __restrict__ W,
    const float* __restrict__ bprev,           // bias applied to INPUT (layer2)
    float* __restrict__ out_param,             // d_out (used when layer==2)
    int NU, int N, int layer)
{
    __shared__ float Ws[64 * 64];              // 16 KB
    __shared__ float xs[128 * 64];             // 32 KB

    const int tid  = threadIdx.x;
    const int base = blockIdx.x * 128;

    // device-side resolution of the acc target (NEVER pass g_acc from host!)
    float* acc_dst = (layer == 1) ? g_acc : out_param;

    // Load W (64x64 row-major: W[k*64 + j])
    for (int i = tid; i < 64 * 16; i += 256)
        ((float4*)Ws)[i] = ((const float4*)W)[i];

    // Load x tile
    for (int f = tid; f < 128 * 16; f += 256) {
        int row  = f >> 4;
        int off  = f & 15;
        int node = base + row;
        float4 v = make_float4(0.f, 0.f, 0.f, 0.f);
        if (node < N) {
            if (layer == 1) {
                const float* src = (node < NU)
                    ? user_emb + (size_t)node * 64
                    : item_emb + (size_t)(node - NU) * 64;
                v = ((const float4*)src)[off];
            } else {
                float4 a  = ((const float4*)g_acc)[(size_t)node * 16 + off];
                float  dv = g_dinv[node];
                float4 bb = ((const float4*)bprev)[off];
                v.x = fmaf(dv, a.x, bb.x);
                v.y = fmaf(dv, a.y, bb.y);
                v.z = fmaf(dv, a.z, bb.z);
                v.w = fmaf(dv, a.w, bb.w);
            }
        }
        ((float4*)xs)[f] = v;
    }
    __syncthreads();

    const int col4 = tid & 15;                 // cols [4*col4, 4*col4+4)
    const int ng   = tid >> 4;                 // nodes [ng*8, ng*8+8)

    float4 acc[8];
    #pragma unroll
    for (int i = 0; i < 8; ++i) acc[i] = make_float4(0.f, 0.f, 0.f, 0.f);

    const float* xr = &xs[(ng * 8) * 64];
    #pragma unroll 4
    for (int k = 0; k < 64; ++k) {
        float4 w4 = *(const float4*)&Ws[k * 64 + col4 * 4];
        #pragma unroll
        for (int i = 0; i < 8; ++i) {
            float xv = xr[i * 64 + k];
            acc[i].x = fmaf(xv, w4.x, acc[i].x);
            acc[i].y = fmaf(xv, w4.y, acc[i].y);
            acc[i].z = fmaf(xv, w4.z, acc[i].z);
            acc[i].w = fmaf(xv, w4.w, acc[i].w);
        }
    }

    #pragma unroll
    for (int i = 0; i < 8; ++i) {
        int node = base + ng * 8 + i;
        if (node < N) {
            float dv = g_dinv[node];
            float4 o = make_float4(dv * acc[i].x, dv * acc[i].y,
                                   dv * acc[i].z, dv * acc[i].w);
            ((float4*)g_g)[(size_t)node * 16 + col4]     = o;   // gather source
            ((float4*)acc_dst)[(size_t)node * 16 + col4] = o;   // self-loop init
        }
    }
}

// ------------------------------- scatter -----------------------------------
// 16 threads per edge; each gathers one float4 of g[row] and RED-adds it
// into acc[col]. g (51 MB) + acc (51 MB) are L2-resident.
__global__ __launch_bounds__(256) void scatter_kernel(
    float* __restrict__ outbuf, int to_out, int E)
{
    unsigned t = blockIdx.x * blockDim.x + threadIdx.x;
    unsigned e = t >> 4;
    if (e >= (unsigned)E) return;
    int j = t & 15;
    int r = g_e32[e];
    int c = g_e32[E + e];
    float4 v = ((const float4*)g_g)[(size_t)r * 16 + j];
    float4* dst = to_out ? (float4*)outbuf : (float4*)g_acc;  // device-side symbol
    float4* p = dst + (size_t)c * 16 + j;
    asm volatile("red.global.add.v4.f32 [%0], {%1, %2, %3, %4};"
                 :: "l"(p), "f"(v.x), "f"(v.y), "f"(v.z), "f"(v.w)
                 : "memory");
}

// ------------------------------- finalize ----------------------------------
__global__ void finalize_kernel(float* __restrict__ out,
                                const float* __restrict__ b2, int n) {
    int t = blockIdx.x * blockDim.x + threadIdx.x;
    if (t >= n * 16) return;
    int node = t >> 4;
    int off  = t & 15;
    float4 v  = ((float4*)out)[t];
    float  dv = g_dinv[node];
    float4 bb = ((const float4*)b2)[off];
    v.x = fmaf(dv, v.x, bb.x);
    v.y = fmaf(dv, v.y, bb.y);
    v.z = fmaf(dv, v.z, bb.z);
    v.w = fmaf(dv, v.w, bb.w);
    ((float4*)out)[t] = v;
}

// ------------------------------- launch ------------------------------------
extern "C" void kernel_launch(void* const* d_in, const int* in_sizes, int n_in,
                              void* d_out, int out_size) {
    // Size-signature-based input mapping (robust to metadata ordering):
    int ie = -1, iu = -1, ii = -1, iw1 = -1, iw2 = -1, ib1 = -1, ib2 = -1;
    for (int i = 0; i < n_in; ++i) {
        int s = in_sizes[i];
        if (s == D * D)      { if (iw1 < 0) iw1 = i; else if (iw2 < 0) iw2 = i; }
        else if (s == D)     { if (ib1 < 0) ib1 = i; else if (ib2 < 0) ib2 = i; }
    }
    for (int i = 0; i < n_in && ii < 0; ++i) {
        if (i == iw1 || i == iw2 || i == ib1 || i == ib2) continue;
        for (int jj = i + 1; jj < n_in; ++jj) {
            if (jj == iw1 || jj == iw2 || jj == ib1 || jj == ib2) continue;
            if (in_sizes[i] == in_sizes[jj] && in_sizes[i] % D == 0) {
                iu = i; ii = jj; break;
            }
        }
    }
    for (int i = 0; i < n_in; ++i)
        if (i != iu && i != ii && i != iw1 && i != iw2 && i != ib1 && i != ib2)
            { ie = i; break; }
    if (ie < 0 || iu < 0 || ii < 0 || iw1 < 0 || iw2 < 0 || ib1 < 0 || ib2 < 0) {
        ie = 0; iu = 1; ii = 2; iw1 = 3; ib1 = 4; iw2 = 5; ib2 = 6;
    }

    const void*  edge_raw = d_in[ie];
    const float* user_emb = (const float*)d_in[iu];
    const float* item_emb = (const float*)d_in[ii];
    const float* W1       = (const float*)d_in[iw1];
    const float* b1       = (const float*)d_in[ib1];
    const float* W2       = (const float*)d_in[iw2];
    const float* b2       = (const float*)d_in[ib2];
    float* out = (float*)d_out;

    const int NU = in_sizes[iu] / D;
    const int NI = in_sizes[ii] / D;
    const int N  = NU + NI;
    int E = in_sizes[ie] / 2;
    if (E > MAXE) E = MAXE;

    // 0) normalize edge indices to int32
    detect_kernel<<<1, 256>>>((const unsigned int*)edge_raw);
    convert_kernel<<<(2 * E + 255) / 256, 256>>>(edge_raw, 2 * E, N);

    // 1) degrees / dinv
    deg_init_kernel<<<(N + 255) / 256, 256>>>(N);
    deg_count_kernel<<<(E + 255) / 256, 256>>>(E);
    dinv_kernel<<<(N + 255) / 256, 256>>>(N);

    const int tblocks = (N + 127) / 128;
    const int sblocks = (int)(((long long)E * 16 + 255) / 256);

    // 2) layer 1: g = (x@W1)*dinv ; g_acc = g (self-loop) ; g_acc[col] += g[row]
    transform_kernel<<<tblocks, 256>>>(user_emb, item_emb, W1, b1,
                                       out /*unused*/, NU, N, /*layer=*/1);
    scatter_kernel<<<sblocks, 256>>>(out, /*to_out=*/0, E);

    // 3) layer 2: x2 = dinv*g_acc + b1 ; g = (x2@W2)*dinv ; out = g ; out[col] += g[row]
    transform_kernel<<<tblocks, 256>>>(user_emb, item_emb, W2, b1,
                                       out, NU, N, /*layer=*/2);
    scatter_kernel<<<sblocks, 256>>>(out, /*to_out=*/1, E);

    // 4) out = dinv*out + b2
    finalize_kernel<<<(N * 16 + 255) / 256, 256>>>(out, b2, N);
}

// round 12
// speedup vs baseline: 1.3679x; 1.3679x over previous
#include <cuda_runtime.h>
#include <cstdint>

// ---------------------------------------------------------------------------
// LightGCN / 2-layer GCN on GB300 — R10: CSR segmented-sum aggregation.
//   x = concat(user_emb, item_emb)            [N,64]
//   deg[c] = indeg[c] + 1 (self loop);  dinv = rsqrt(deg)
//   layer: g = (x@W)*dinv;  out[c] = dinv[c]*( g[c] + sum_{e:col=c} g[row_e] ) + b
// R9 was scatter-bound: 19.2M RED.v4/layer at ~1.29 cyc/lane = ~84us issue
// floor per scatter. R10 builds a col-grouped CSR (count -> scan -> fill) and
// replaces atomics with register accumulation + one STG.128 per (node,j).
// dinv*acc+b is fused into the segsum epilogue (finalize kernel removed).
// ---------------------------------------------------------------------------

#define D 64
#define MAXN 200064
#define MAXE 1200000
#define SCAN_BLK 1024            // elements per scan block
#define MAXSB 256                // max scan blocks (200064/1024 = 196)

__device__ int   g_flag;                       // 1 => edge_index is int64
__device__ int   g_e32[2 * MAXE];              // [0,E): row, [E,2E): col
__device__ int   g_indeg[MAXN];                // in-degree WITHOUT self loop
__device__ int   g_rowptr[MAXN];               // exclusive prefix of indeg
__device__ int   g_cursor[MAXN];               // fill cursors (copy of rowptr)
__device__ int   g_nbr[MAXE];                  // CSR: row indices grouped by col
__device__ int   g_bsum[MAXSB];                // scan block sums
__device__ float g_dinv[MAXN];
__device__ float g_g[(size_t)MAXN * D];        // pre-scaled transformed feats
__device__ float g_acc[(size_t)MAXN * D];      // layer-1 output (x2)

// --------------------------- dtype detection -------------------------------
// int64 little-endian with values < 2^31: every odd 32-bit word is 0.
// For int32 data the odd words are random node indices; all-256-zero is
// impossible (p ~ (1/200000)^256). g_flag=1 <=> 8-byte stride.
__global__ void detect_kernel(const unsigned int* __restrict__ raw) {
    __shared__ int any_nonzero;
    if (threadIdx.x == 0) any_nonzero = 0;
    __syncthreads();
    if (raw[2 * threadIdx.x + 1] != 0u) atomicExch(&any_nonzero, 1);
    __syncthreads();
    if (threadIdx.x == 0) g_flag = (any_nonzero == 0) ? 1 : 0;
}

__global__ void convert_kernel(const void* __restrict__ raw, int n2e, int N) {
    int i = blockIdx.x * blockDim.x + threadIdx.x;
    if (i >= n2e) return;
    long long v;
    if (g_flag) v = ((const long long*)raw)[i];
    else        v = (long long)((const int*)raw)[i];
    int vi = (int)v;
    if ((unsigned)vi >= (unsigned)N) vi = 0;   // corruption insurance
    g_e32[i] = vi;
}

// ----------------------- degree count + CSR build --------------------------
__global__ void zero_indeg_kernel(int n) {
    int i = blockIdx.x * blockDim.x + threadIdx.x;
    if (i < n) g_indeg[i] = 0;
}

__global__ void deg_count_kernel(int E) {
    int e = blockIdx.x * blockDim.x + threadIdx.x;
    if (e < E) atomicAdd(&g_indeg[g_e32[E + e]], 1);
}

// pass1: per-block (1024 elems) exclusive scan of indeg -> rowptr; block sums.
__global__ __launch_bounds__(256) void scan1_kernel(int N) {
    __shared__ int s[256];
    const int tid  = threadIdx.x;
    const int base = blockIdx.x * SCAN_BLK + tid * 4;
    int a0 = (base + 0 < N) ? g_indeg[base + 0] : 0;
    int a1 = (base + 1 < N) ? g_indeg[base + 1] : 0;
    int a2 = (base + 2 < N) ? g_indeg[base + 2] : 0;
    int a3 = (base + 3 < N) ? g_indeg[base + 3] : 0;
    int tsum = a0 + a1 + a2 + a3;
    s[tid] = tsum;
    __syncthreads();
    #pragma unroll
    for (int o = 1; o < 256; o <<= 1) {
        int v = (tid >= o) ? s[tid - o] : 0;
        __syncthreads();
        s[tid] += v;
        __syncthreads();
    }
    int excl = s[tid] - tsum;                  // exclusive within block
    if (base + 0 < N) g_rowptr[base + 0] = excl;
    if (base + 1 < N) g_rowptr[base + 1] = excl + a0;
    if (base + 2 < N) g_rowptr[base + 2] = excl + a0 + a1;
    if (base + 3 < N) g_rowptr[base + 3] = excl + a0 + a1 + a2;
    if (tid == 255) g_bsum[blockIdx.x] = s[255];
}

// pass2: exclusive scan of block sums (single block).
__global__ __launch_bounds__(256) void scan2_kernel(int nb) {
    __shared__ int s[256];
    const int tid = threadIdx.x;
    int v0 = (tid < nb) ? g_bsum[tid] : 0;
    s[tid] = v0;
    __syncthreads();
    #pragma unroll
    for (int o = 1; o < 256; o <<= 1) {
        int v = (tid >= o) ? s[tid - o] : 0;
        __syncthreads();
        s[tid] += v;
        __syncthreads();
    }
    if (tid < nb) g_bsum[tid] = s[tid] - v0;   // exclusive
}

// pass3: add block offsets; init cursors; compute dinv = rsqrt(indeg+1).
__global__ void scan3_kernel(int N) {
    int i = blockIdx.x * blockDim.x + threadIdx.x;
    if (i >= N) return;
    int rp = g_rowptr[i] + g_bsum[i / SCAN_BLK];
    g_rowptr[i] = rp;
    g_cursor[i] = rp;
    g_dinv[i]   = rsqrtf((float)(g_indeg[i] + 1));
}

__global__ void csr_fill_kernel(int E) {
    int e = blockIdx.x * blockDim.x + threadIdx.x;
    if (e >= E) return;
    int r = g_e32[e];
    int c = g_e32[E + e];
    int pos = atomicAdd(&g_cursor[c], 1);
    g_nbr[pos] = r;
}

// ------------------------------ transform ----------------------------------
// Per block: 128 nodes x 64 cols. 256 threads; thread = (node_group 0..15) x
// (col4 0..15); each thread accumulates 8 nodes x 4 cols in registers.
// layer==1: input = embeddings. layer==2: input = g_acc (x2, already scaled
// and biased by segsum L1). Writes g = (x@W)*dinv to g_g only.
__global__ __launch_bounds__(256) void transform_kernel(
    const float* __restrict__ user_emb,
    const float* __restrict__ item_emb,
    const float* __restrict__ W,
    int NU, int N, int layer)
{
    __shared__ float Ws[64 * 64];              // 16 KB
    __shared__ float xs[128 * 64];             // 32 KB

    const int tid  = threadIdx.x;
    const int base = blockIdx.x * 128;

    for (int i = tid; i < 64 * 16; i += 256)
        ((float4*)Ws)[i] = ((const float4*)W)[i];

    for (int f = tid; f < 128 * 16; f += 256) {
        int row  = f >> 4;
        int off  = f & 15;
        int node = base + row;
        float4 v = make_float4(0.f, 0.f, 0.f, 0.f);
        if (node < N) {
            if (layer == 1) {
                const float* src = (node < NU)
                    ? user_emb + (size_t)node * 64
                    : item_emb + (size_t)(node - NU) * 64;
                v = ((const float4*)src)[off];
            } else {
                v = ((const float4*)g_acc)[(size_t)node * 16 + off];
            }
        }
        ((float4*)xs)[f] = v;
    }
    __syncthreads();

    const int col4 = tid & 15;
    const int ng   = tid >> 4;

    float4 acc[8];
    #pragma unroll
    for (int i = 0; i < 8; ++i) acc[i] = make_float4(0.f, 0.f, 0.f, 0.f);

    const float* xr = &xs[(ng * 8) * 64];
    #pragma unroll 4
    for (int k = 0; k < 64; ++k) {
        float4 w4 = *(const float4*)&Ws[k * 64 + col4 * 4];
        #pragma unroll
        for (int i = 0; i < 8; ++i) {
            float xv = xr[i * 64 + k];
            acc[i].x = fmaf(xv, w4.x, acc[i].x);
            acc[i].y = fmaf(xv, w4.y, acc[i].y);
            acc[i].z = fmaf(xv, w4.z, acc[i].z);
            acc[i].w = fmaf(xv, w4.w, acc[i].w);
        }
    }

    #pragma unroll
    for (int i = 0; i < 8; ++i) {
        int node = base + ng * 8 + i;
        if (node < N) {
            float dv = g_dinv[node];
            ((float4*)g_g)[(size_t)node * 16 + col4] =
                make_float4(dv * acc[i].x, dv * acc[i].y,
                            dv * acc[i].z, dv * acc[i].w);
        }
    }
}

// --------------------------- segmented sum ---------------------------------
// 16 threads per node (thread j owns float4 j of the 64-dim row). Register
// accumulation over CSR neighbors, self-loop as initializer, fused epilogue
// dst[c] = dinv[c]*acc + b. One plain STG.128 per thread — no atomics.
__global__ __launch_bounds__(256) void segsum_kernel(
    const float* __restrict__ bvec,
    float* __restrict__ out_param, int to_out, int N)
{
    int t = blockIdx.x * blockDim.x + threadIdx.x;
    int node = t >> 4;
    if (node >= N) return;
    int j = t & 15;

    const float4* G = (const float4*)g_g;
    int s = g_rowptr[node];
    int d = g_indeg[node];
    int e = s + d;

    float4 v = G[(size_t)node * 16 + j];       // self loop
    int k = s;
    for (; k + 4 <= e; k += 4) {               // MLP-4 batches
        int r0 = g_nbr[k + 0];
        int r1 = g_nbr[k + 1];
        int r2 = g_nbr[k + 2];
        int r3 = g_nbr[k + 3];
        float4 a0 = G[(size_t)r0 * 16 + j];
        float4 a1 = G[(size_t)r1 * 16 + j];
        float4 a2 = G[(size_t)r2 * 16 + j];
        float4 a3 = G[(size_t)r3 * 16 + j];
        v.x += a0.x + a1.x + a2.x + a3.x;
        v.y += a0.y + a1.y + a2.y + a3.y;
        v.z += a0.z + a1.z + a2.z + a3.z;
        v.w += a0.w + a1.w + a2.w + a3.w;
    }
    for (; k < e; ++k) {
        float4 a = G[(size_t)g_nbr[k] * 16 + j];
        v.x += a.x; v.y += a.y; v.z += a.z; v.w += a.w;
    }

    float  dv = g_dinv[node];
    float4 bb = ((const float4*)bvec)[j];
    v.x = fmaf(dv, v.x, bb.x);
    v.y = fmaf(dv, v.y, bb.y);
    v.z = fmaf(dv, v.z, bb.z);
    v.w = fmaf(dv, v.w, bb.w);

    float4* dst = to_out ? (float4*)out_param : (float4*)g_acc;
    dst[(size_t)node * 16 + j] = v;
}

// ------------------------------- launch ------------------------------------
extern "C" void kernel_launch(void* const* d_in, const int* in_sizes, int n_in,
                              void* d_out, int out_size) {
    // Size-signature-based input mapping (robust to metadata ordering):
    int ie = -1, iu = -1, ii = -1, iw1 = -1, iw2 = -1, ib1 = -1, ib2 = -1;
    for (int i = 0; i < n_in; ++i) {
        int s = in_sizes[i];
        if (s == D * D)      { if (iw1 < 0) iw1 = i; else if (iw2 < 0) iw2 = i; }
        else if (s == D)     { if (ib1 < 0) ib1 = i; else if (ib2 < 0) ib2 = i; }
    }
    for (int i = 0; i < n_in && ii < 0; ++i) {
        if (i == iw1 || i == iw2 || i == ib1 || i == ib2) continue;
        for (int jj = i + 1; jj < n_in; ++jj) {
            if (jj == iw1 || jj == iw2 || jj == ib1 || jj == ib2) continue;
            if (in_sizes[i] == in_sizes[jj] && in_sizes[i] % D == 0) {
                iu = i; ii = jj; break;
            }
        }
    }
    for (int i = 0; i < n_in; ++i)
        if (i != iu && i != ii && i != iw1 && i != iw2 && i != ib1 && i != ib2)
            { ie = i; break; }
    if (ie < 0 || iu < 0 || ii < 0 || iw1 < 0 || iw2 < 0 || ib1 < 0 || ib2 < 0) {
        ie = 0; iu = 1; ii = 2; iw1 = 3; ib1 = 4; iw2 = 5; ib2 = 6;
    }

    const void*  edge_raw = d_in[ie];
    const float* user_emb = (const float*)d_in[iu];
    const float* item_emb = (const float*)d_in[ii];
    const float* W1       = (const float*)d_in[iw1];
    const float* b1       = (const float*)d_in[ib1];
    const float* W2       = (const float*)d_in[iw2];
    const float* b2       = (const float*)d_in[ib2];
    float* out = (float*)d_out;

    const int NU = in_sizes[iu] / D;
    const int NI = in_sizes[ii] / D;
    const int N  = NU + NI;
    int E = in_sizes[ie] / 2;
    if (E > MAXE) E = MAXE;

    const int nb = (N + SCAN_BLK - 1) / SCAN_BLK;   // scan blocks (<=196)

    // 0) normalize edge indices to int32
    detect_kernel<<<1, 256>>>((const unsigned int*)edge_raw);
    convert_kernel<<<(2 * E + 255) / 256, 256>>>(edge_raw, 2 * E, N);

    // 1) CSR build: indeg -> exclusive scan -> fill; dinv fused in scan3
    zero_indeg_kernel<<<(N + 255) / 256, 256>>>(N);
    deg_count_kernel<<<(E + 255) / 256, 256>>>(E);
    scan1_kernel<<<nb, 256>>>(N);
    scan2_kernel<<<1, 256>>>(nb);
    scan3_kernel<<<(N + 255) / 256, 256>>>(N);
    csr_fill_kernel<<<(E + 255) / 256, 256>>>(E);

    const int tblocks = (N + 127) / 128;
    const int gblocks = (N * 16 + 255) / 256;

    // 2) layer 1: g = (x@W1)*dinv ; x2 = dinv*(g[c]+sum g[nbr]) + b1 -> g_acc
    transform_kernel<<<tblocks, 256>>>(user_emb, item_emb, W1, NU, N, 1);
    segsum_kernel<<<gblocks, 256>>>(b1, out, /*to_out=*/0, N);

    // 3) layer 2: g = (x2@W2)*dinv ; out = dinv*(g[c]+sum g[nbr]) + b2
    transform_kernel<<<tblocks, 256>>>(user_emb, item_emb, W2, NU, N, 2);
    segsum_kernel<<<gblocks, 256>>>(b2, out, /*to_out=*/1, N);
}